// round 9
// baseline (speedup 1.0000x reference)
#include <cuda_runtime.h>

// CorefScore: out[m,k] = ment[m] + ment[j] + pair(m,j),  j = m - K + k, masked to -1e9 if j<0
//             out[m,K] = 0
// Fixed shapes: M=2048, D=900, H=150, K=50.
//
// Design: packed fp32x2 math (fma.rn.f32x2). R7: Ws holds Q = xm*W1c (scale
// fused into staging). R8: precompute m-tile 8, grid 256 (occupancy fix).
// R9: Xj staged PRE-DUPLICATED as u64 (x,x) pairs -> inner loop is pure
// LDS.64 + ffma2 (no pack2): issue slots 28 -> 23 per warp-dd. Bank audit:
// row stride 62 words -> kg banks {0,22,12,2,24,14,4,26,16,6}, conflict-free.

#define M_SIZE 2048
#define D_SIZE 900
#define H_SIZE 150
#define K_SIZE 50
#define DC     30          // d-chunk (900 = 30*30)
#define ROWS   8           // m-rows per precompute CTA
#define NEG_VAL (-1000000000.0f)

typedef unsigned long long u64;

// ---- f32x2 helpers --------------------------------------------------------
__device__ __forceinline__ u64 pack2(float lo, float hi) {
    u64 r; asm("mov.b64 %0, {%1, %2};" : "=l"(r) : "f"(lo), "f"(hi)); return r;
}
__device__ __forceinline__ void unpack2(float& lo, float& hi, u64 v) {
    asm("mov.b64 {%0, %1}, %2;" : "=f"(lo), "=f"(hi) : "l"(v));
}
__device__ __forceinline__ u64 ffma2(u64 a, u64 b, u64 c) {
    u64 d; asm("fma.rn.f32x2 %0, %1, %2, %3;" : "=l"(d) : "l"(a), "l"(b), "l"(c)); return d;
}

// Scratch (allocation-free per harness rules)
__device__ float g_A1[M_SIZE * H_SIZE];   // X@W1a + b1p
__device__ float g_B1[M_SIZE * H_SIZE];   // X@W1b
__device__ float g_ment[M_SIZE];          // relu(X@w1m+b1m)@w2m + b2m

// ---------------------------------------------------------------------------
// Kernel 1: precompute A1, B1, ment.
// Grid: M/8 = 256 blocks, 160 threads (thread = h). 8 m-rows per block.
// Xs staged TRANSPOSED so mi-pairs are contiguous -> LDS.64 (warp-broadcast,
// conflict-free) + fma.rn.f32x2 packing over mi (4 packed accumulators each).
// ---------------------------------------------------------------------------
__global__ __launch_bounds__(160) void precompute_kernel(
    const float* __restrict__ X,   const float* __restrict__ w1m,
    const float* __restrict__ b1m, const float* __restrict__ w2m,
    const float* __restrict__ b2m, const float* __restrict__ w1p,
    const float* __restrict__ b1p)
{
    __shared__ __align__(16) float Xst[DC][ROWS];   // [dd][mi], row = 32B
    __shared__ float sred[5][ROWS];

    const int tid = threadIdx.x;
    const int m0  = blockIdx.x * ROWS;
    const int h   = tid;

    u64 am2[4], aa2[4], ab2[4];
#pragma unroll
    for (int i = 0; i < 4; i++) { am2[i] = 0ull; aa2[i] = 0ull; ab2[i] = 0ull; }

    const float* __restrict__ W1a = w1p;                       // rows [0, D)
    const float* __restrict__ W1b = w1p + D_SIZE * H_SIZE;     // rows [D, 2D)

    for (int d0 = 0; d0 < D_SIZE; d0 += DC) {
        __syncthreads();
        // Stage 8*30 = 240 elems with 160 threads: idx = tid, tid+160.
        {
            const int mi0 = tid / DC, dd0 = tid - (tid / DC) * DC;
            Xst[dd0][mi0] = X[(m0 + mi0) * D_SIZE + d0 + dd0];
            if (tid < 80) {
                const int idx = tid + 160;
                const int mi1 = idx / DC, dd1 = idx - (idx / DC) * DC;
                Xst[dd1][mi1] = X[(m0 + mi1) * D_SIZE + d0 + dd1];
            }
        }
        __syncthreads();
        if (h < H_SIZE) {
#pragma unroll 6
            for (int dd = 0; dd < DC; dd++) {
                const int d = d0 + dd;
                const float wm = w1m[d * H_SIZE + h];
                const float wa = W1a[d * H_SIZE + h];
                const float wb = W1b[d * H_SIZE + h];
                const u64 wm2 = pack2(wm, wm);
                const u64 wa2 = pack2(wa, wa);
                const u64 wb2 = pack2(wb, wb);
                const u64* xp = reinterpret_cast<const u64*>(&Xst[dd][0]);
#pragma unroll
                for (int i = 0; i < 4; i++) {
                    const u64 x2 = xp[i];       // LDS.64, warp-broadcast
                    am2[i] = ffma2(x2, wm2, am2[i]);
                    aa2[i] = ffma2(x2, wa2, aa2[i]);
                    ab2[i] = ffma2(x2, wb2, ab2[i]);
                }
            }
        }
    }

    // Epilogue: write A1/B1, deterministic reduction for ment.
    float v[ROWS];
    if (h < H_SIZE) {
        const float bh = b1m[h], wh = w2m[h], bp = b1p[h];
#pragma unroll
        for (int i = 0; i < 4; i++) {
            float aal, aah, abl, abh2, aml, amh;
            unpack2(aal, aah, aa2[i]);
            unpack2(abl, abh2, ab2[i]);
            unpack2(aml, amh, am2[i]);
            g_A1[(m0 + 2 * i    ) * H_SIZE + h] = aal + bp;
            g_A1[(m0 + 2 * i + 1) * H_SIZE + h] = aah + bp;
            g_B1[(m0 + 2 * i    ) * H_SIZE + h] = abl;
            g_B1[(m0 + 2 * i + 1) * H_SIZE + h] = abh2;
            v[2 * i    ] = fmaxf(aml + bh, 0.f) * wh;
            v[2 * i + 1] = fmaxf(amh + bh, 0.f) * wh;
        }
    } else {
#pragma unroll
        for (int mi = 0; mi < ROWS; mi++) v[mi] = 0.f;
    }

    const int lane = tid & 31, warp = tid >> 5;
#pragma unroll
    for (int mi = 0; mi < ROWS; mi++) {
#pragma unroll
        for (int off = 16; off > 0; off >>= 1)
            v[mi] += __shfl_down_sync(0xFFFFFFFFu, v[mi], off);
    }
    if (lane == 0) {
#pragma unroll
        for (int mi = 0; mi < ROWS; mi++) sred[warp][mi] = v[mi];
    }
    __syncthreads();
    if (tid < ROWS) {
        float s = b2m[0];
#pragma unroll
        for (int w = 0; w < 5; w++) s += sred[w][tid];
        g_ment[m0 + tid] = s;
    }
}

// ---------------------------------------------------------------------------
// Kernel 2: main pairwise score. One block per mention m.
// C[k,h] = sum_d (X[m,d]*X[j,d]) * W1c[d,h],  j = m-K+k (clamped; masked later)
// Thread tile: 5 k x 6 h (= 3 packed h-pairs), 250 active threads.
// Ws holds Q[dd][hh] = Xm[d0+dd] * W1c[d0+dd][hh] (scale fused into staging).
// XjD holds duplicated pairs (x,x) as u64 -> inner loop per dd per thread:
// 15 fma.f32x2 (fma pipe) + 8 LDS (5x LDS.64 XjD + 3x LDS.64 Q), no packs.
// ---------------------------------------------------------------------------
__global__ __launch_bounds__(256) void score_kernel(
    const float* __restrict__ X,   const float* __restrict__ w1p,
    const float* __restrict__ w2p, const float* __restrict__ b2p,
    float* __restrict__ out)
{
    __shared__ __align__(16) float Xm[D_SIZE];          // 3.6 KB
    __shared__ __align__(16) u64 XjD[K_SIZE][DC + 1];   // dup pairs, 12.4 KB
    __shared__ __align__(16) float Ws[DC][H_SIZE];      // Q = xm*W1c, 18 KB
    __shared__ float red[K_SIZE][26];                   // 5.2 KB

    const float* __restrict__ W1c = w1p + 2 * D_SIZE * H_SIZE;

    const int tid = threadIdx.x;
    const int m   = blockIdx.x;

    // Xm fully staged before the loop; the loop-top barrier orders it
    // against the first Ws staging read below.
    for (int i = tid; i < D_SIZE; i += 256) Xm[i] = X[m * D_SIZE + i];

    const int  kg     = tid % 10;     // k = kg*5 + i
    const int  hg     = tid / 10;     // h = hg*6 + (2q, 2q+1), hg < 25
    const bool active = (tid < 250);

    // Staging indices decomposed once (no per-iter div/mod).
    const int xj_k0  = tid / DC;
    const int xj_dd0 = tid - xj_k0 * DC;
    const int ws_dd0 = tid / H_SIZE;
    const int ws_hh0 = tid - ws_dd0 * H_SIZE;

    u64 acc2[5][3];
#pragma unroll
    for (int i = 0; i < 5; i++)
#pragma unroll
        for (int q = 0; q < 3; q++) acc2[i][q] = 0ull;

    for (int d0 = 0; d0 < D_SIZE; d0 += DC) {
        __syncthreads();
        // Stage neighbor rows X[j] as duplicated (x,x) u64 pairs,
        // j = m-50+k (clamped to 0; masked in epilogue).
        {
            int k = xj_k0, dd = xj_dd0;
#pragma unroll
            for (int r = 0; r < 6 && k < K_SIZE; r++) {   // 1500/256 -> 5..6 iters
                const int j  = m - K_SIZE + k;
                const int jc = j < 0 ? 0 : j;
                const float x = X[jc * D_SIZE + d0 + dd];
                XjD[k][dd] = pack2(x, x);
                k += 8; dd += 16;                          // stride 256 = 8*30+16
                if (dd >= DC) { dd -= DC; k += 1; }
            }
        }
        // Stage Q = xm * W1c chunk (scale fused into the staging store).
        {
            int dd = ws_dd0, hh = ws_hh0;
#pragma unroll
            for (int r = 0; r < 18 && dd < DC; r++) {      // 4500/256 -> 17..18 iters
                Ws[dd][hh] = W1c[(d0 + dd) * H_SIZE + hh] * Xm[d0 + dd];
                dd += 1; hh += 106;                        // stride 256 = 1*150+106
                if (hh >= H_SIZE) { hh -= H_SIZE; dd += 1; }
            }
        }
        __syncthreads();

        if (active) {
#pragma unroll 6
            for (int dd = 0; dd < DC; dd++) {
                // 3 packed Q pairs: LDS.64, 4 distinct hg/warp -> conflict-free
                const u64* qp = reinterpret_cast<const u64*>(&Ws[dd][hg * 6]);
                const u64 q0 = qp[0], q1 = qp[1], q2 = qp[2];
#pragma unroll
                for (int i = 0; i < 5; i++) {
                    const u64 x2 = XjD[kg * 5 + i][dd];   // LDS.64, dedup'd
                    acc2[i][0] = ffma2(x2, q0, acc2[i][0]);
                    acc2[i][1] = ffma2(x2, q1, acc2[i][1]);
                    acc2[i][2] = ffma2(x2, q2, acc2[i][2]);
                }
            }
        }
    }

    __syncthreads();
    // Partial pair scores: relu(C + A1[m] + B1[j]) . w2p over this thread's 6 h.
    // A1[m] and w2p are invariant across the 5 k's -> hoisted to registers.
    if (active) {
        float a1r[6], w2r[6];
#pragma unroll
        for (int jj = 0; jj < 6; jj++) {
            const int hh = hg * 6 + jj;
            a1r[jj] = g_A1[m * H_SIZE + hh];
            w2r[jj] = w2p[hh];
        }
#pragma unroll
        for (int i = 0; i < 5; i++) {
            const int k  = kg * 5 + i;
            const int j  = m - K_SIZE + k;
            const int jc = j < 0 ? 0 : j;
            const float* __restrict__ b1row = &g_B1[jc * H_SIZE + hg * 6];
            float s = 0.f;
#pragma unroll
            for (int q = 0; q < 3; q++) {
                float cl, ch;
                unpack2(cl, ch, acc2[i][q]);
                const float z0 = cl + a1r[2 * q    ] + b1row[2 * q    ];
                const float z1 = ch + a1r[2 * q + 1] + b1row[2 * q + 1];
                s = fmaf(fmaxf(z0, 0.f), w2r[2 * q    ], s);
                s = fmaf(fmaxf(z1, 0.f), w2r[2 * q + 1], s);
            }
            red[k][hg] = s;
        }
    }
    __syncthreads();

    if (tid < K_SIZE) {
        const int k = tid;
        const int j = m - K_SIZE + k;
        float pair = b2p[0];
#pragma unroll
        for (int g = 0; g < 25; g++) pair += red[k][g];
        const float sc = (j >= 0) ? (g_ment[m] + g_ment[j] + pair) : NEG_VAL;
        out[m * (K_SIZE + 1) + k] = sc;
    }
    if (tid == K_SIZE) out[m * (K_SIZE + 1) + K_SIZE] = 0.f;  // dummy column
}

// ---------------------------------------------------------------------------
extern "C" void kernel_launch(void* const* d_in, const int* in_sizes, int n_in,
                              void* d_out, int out_size)
{
    const float* X    = (const float*)d_in[0];
    const float* w1m  = (const float*)d_in[1];
    const float* b1m  = (const float*)d_in[2];
    const float* w2m  = (const float*)d_in[3];
    const float* b2m  = (const float*)d_in[4];
    const float* w1p  = (const float*)d_in[5];
    const float* b1p  = (const float*)d_in[6];
    const float* w2p  = (const float*)d_in[7];
    const float* b2p  = (const float*)d_in[8];
    float*       out  = (float*)d_out;

    precompute_kernel<<<M_SIZE / ROWS, 160>>>(X, w1m, b1m, w2m, b2m, w1p, b1p);
    score_kernel<<<M_SIZE, 256>>>(X, w1p, w2p, b2p, out);
}